// round 11
// baseline (speedup 1.0000x reference)
#include <cuda_runtime.h>
#include <cuda_bf16.h>
#include <cstdint>

#define DI __device__ __forceinline__

static constexpr int   NN     = 8192;
static constexpr int   DD     = 256;
static constexpr float EPS    = 1e-8f;
static constexpr float THR    = 1e-6f;
static constexpr float LN_EPS = 1e-5f;

// ---------------- device scratch ----------------
__device__ float          g_part[2 * NN];
__device__ float          g_inv[NN];
__device__ float          g_wsum[NN];
__device__ float          g_T[(size_t)NN * DD];
__device__ __nv_bfloat16  g_Tbf[(size_t)NN * DD];
__device__ __nv_bfloat16  g_Winb[DD * DD];
__device__ __nv_bfloat16  g_Woutb[DD * DD];
__device__ float          g_numA[(size_t)NN * DD];
__device__ float          g_numB[(size_t)NN * DD];
__device__ float          g_numC[(size_t)NN * DD];

// ---------------- helpers ----------------
DI uint32_t smem_u32(const void* p) {
    uint32_t a;
    asm("{ .reg .u64 t; cvta.to.shared.u64 t, %1; cvt.u32.u64 %0, t; }" : "=r"(a) : "l"(p));
    return a;
}
DI void ldsm4t(uint32_t* r, uint32_t addr) {
    asm volatile("ldmatrix.sync.aligned.m8n8.x4.trans.shared.b16 {%0,%1,%2,%3}, [%4];"
        : "=r"(r[0]), "=r"(r[1]), "=r"(r[2]), "=r"(r[3]) : "r"(addr));
}
DI void ldsm4(uint32_t* r, uint32_t addr) {
    asm volatile("ldmatrix.sync.aligned.m8n8.x4.shared.b16 {%0,%1,%2,%3}, [%4];"
        : "=r"(r[0]), "=r"(r[1]), "=r"(r[2]), "=r"(r[3]) : "r"(addr));
}
DI void mma_bf16(float* c, const uint32_t* a, const uint32_t* b) {
    asm volatile(
        "mma.sync.aligned.m16n8k16.row.col.f32.bf16.bf16.f32 "
        "{%0,%1,%2,%3}, {%4,%5,%6,%7}, {%8,%9}, {%0,%1,%2,%3};"
        : "+f"(c[0]), "+f"(c[1]), "+f"(c[2]), "+f"(c[3])
        : "r"(a[0]), "r"(a[1]), "r"(a[2]), "r"(a[3]), "r"(b[0]), "r"(b[1]));
}
DI uint32_t bf2u(float lo, float hi) {
    uint32_t r;
    asm("cvt.rn.bf16x2.f32 %0, %1, %2;" : "=r"(r) : "f"(hi), "f"(lo));
    return r;
}
DI uint4 cvt8bf(float4 a, float4 b) {
    uint4 u;
    u.x = bf2u(a.x, a.y); u.y = bf2u(a.z, a.w);
    u.z = bf2u(b.x, b.y); u.w = bf2u(b.z, b.w);
    return u;
}
DI void cp16(uint32_t smem_dst, const void* gptr) {
    asm volatile("cp.async.cg.shared.global [%0], [%1], 16;" :: "r"(smem_dst), "l"(gptr) : "memory");
}

// ================= kernel 1: column sums of M =================
__global__ void colsum_kernel(const float* __restrict__ M) {
    __shared__ float red[8 * 128];
    int tid = threadIdx.x;
    int it = blockIdx.x >> 1, half = blockIdx.x & 1;
    int i0 = it * 128;
    int rg = tid >> 5, i4 = (tid & 31) * 4;

    float a0 = 0.f, a1 = 0.f, a2 = 0.f, a3 = 0.f;
    int rbeg = half * 4096 + rg, rend = half * 4096 + 4096;
    for (int r = rbeg; r < rend; r += 32) {
        float4 m0 = *(const float4*)&M[(size_t)(r     ) * NN + i0 + i4];
        float4 m1 = *(const float4*)&M[(size_t)(r +  8) * NN + i0 + i4];
        float4 m2 = *(const float4*)&M[(size_t)(r + 16) * NN + i0 + i4];
        float4 m3 = *(const float4*)&M[(size_t)(r + 24) * NN + i0 + i4];
        a0 += m0.x + m1.x + m2.x + m3.x;
        a1 += m0.y + m1.y + m2.y + m3.y;
        a2 += m0.z + m1.z + m2.z + m3.z;
        a3 += m0.w + m1.w + m2.w + m3.w;
    }
    red[rg * 128 + i4 + 0] = a0; red[rg * 128 + i4 + 1] = a1;
    red[rg * 128 + i4 + 2] = a2; red[rg * 128 + i4 + 3] = a3;
    __syncthreads();
    if (tid < 128) {
        float s = 0.f;
#pragma unroll
        for (int g = 0; g < 8; g++) s += red[g * 128 + tid];
        g_part[half * NN + i0 + tid] = s;
    }
}

// ================= kernel 2: prep =================
__global__ void prep_kernel(const float* __restrict__ W_in,
                            const float* __restrict__ W_out) {
    int gid = blockIdx.x * 256 + threadIdx.x;
    if (gid < NN) {
        float s = g_part[gid] + g_part[NN + gid];
        g_inv[gid]  = 1.f / (s + EPS);
        g_wsum[gid] = 0.f;
    }
    g_Winb[gid]  = __float2bfloat16(W_in[gid]);
    g_Woutb[gid] = __float2bfloat16(W_out[gid]);
}

// ================= kernel 3: T = X @ W_in + b_in =================
static constexpr int AP = 40;
static constexpr int BP = 136;

__global__ void __launch_bounds__(256, 1) t_kernel(const float* __restrict__ X,
                                                   const float* __restrict__ b_in) {
    __shared__ __nv_bfloat16 sA[2][128 * AP];
    __shared__ __nv_bfloat16 sB[2][32 * BP];

    int tid = threadIdx.x;
    int j0 = (blockIdx.x >> 1) * 128;
    int d0 = (blockIdx.x & 1) * 128;

    int xj = tid >> 1, xh = (tid & 1) * 16;
    int wk = tid >> 3, wd = (tid & 7) * 16;

    int w = tid >> 5, lane = tid & 31;
    int iw = (w & 3) * 32, dw = (w >> 2) * 64;
    int q = lane >> 3, r7 = lane & 7;
    int l15 = lane & 15, lh = (lane >> 4) * 8;

    float acc[2][8][4] = {};
    float4 xr[4];
    uint4  wr[2];

#pragma unroll
    for (int p = 0; p < 4; p++)
        xr[p] = *(const float4*)&X[(size_t)(j0 + xj) * DD + xh + p * 4];
#pragma unroll
    for (int p = 0; p < 2; p++)
        wr[p] = *(const uint4*)&g_Winb[(size_t)wk * DD + d0 + wd + p * 8];

    *(uint4*)&sA[0][xj * AP + xh]     = cvt8bf(xr[0], xr[1]);
    *(uint4*)&sA[0][xj * AP + xh + 8] = cvt8bf(xr[2], xr[3]);
    *(uint4*)&sB[0][wk * BP + wd]     = wr[0];
    *(uint4*)&sB[0][wk * BP + wd + 8] = wr[1];
    __syncthreads();

    const int NCk = DD / 32;
    int buf = 0;
    for (int c = 0; c < NCk; c++) {
        int nbuf = buf ^ 1;
        if (c + 1 < NCk) {
            int k0 = (c + 1) * 32;
#pragma unroll
            for (int p = 0; p < 4; p++)
                xr[p] = *(const float4*)&X[(size_t)(j0 + xj) * DD + k0 + xh + p * 4];
#pragma unroll
            for (int p = 0; p < 2; p++)
                wr[p] = *(const uint4*)&g_Winb[(size_t)(k0 + wk) * DD + d0 + wd + p * 8];
        }
        uint32_t swb = smem_u32(sA[buf]), stb = smem_u32(sB[buf]);
#pragma unroll
        for (int kk = 0; kk < 32; kk += 16) {
            uint32_t a[2][4];
#pragma unroll
            for (int mb = 0; mb < 2; mb++)
                ldsm4(a[mb], swb + (uint32_t)(((iw + mb * 16 + l15) * AP + kk + lh) * 2));
#pragma unroll
            for (int nbp = 0; nbp < 4; nbp++) {
                uint32_t b[4];
                ldsm4t(b, stb + (uint32_t)(((kk + (q & 1) * 8 + r7) * BP + dw + (nbp * 2 + (q >> 1)) * 8) * 2));
                mma_bf16(acc[0][2 * nbp],     a[0], b);
                mma_bf16(acc[1][2 * nbp],     a[1], b);
                mma_bf16(acc[0][2 * nbp + 1], a[0], b + 2);
                mma_bf16(acc[1][2 * nbp + 1], a[1], b + 2);
            }
        }
        if (c + 1 < NCk) {
            *(uint4*)&sA[nbuf][xj * AP + xh]     = cvt8bf(xr[0], xr[1]);
            *(uint4*)&sA[nbuf][xj * AP + xh + 8] = cvt8bf(xr[2], xr[3]);
            *(uint4*)&sB[nbuf][wk * BP + wd]     = wr[0];
            *(uint4*)&sB[nbuf][wk * BP + wd + 8] = wr[1];
        }
        __syncthreads();
        buf = nbuf;
    }

    int gi = lane >> 2, gk = (lane & 3) * 2;
#pragma unroll
    for (int mb = 0; mb < 2; mb++)
#pragma unroll
        for (int nb = 0; nb < 8; nb++) {
            int dg = d0 + dw + nb * 8 + gk;
            float2 b2 = *(const float2*)&b_in[dg];
            float v0 = acc[mb][nb][0] + b2.x, v1 = acc[mb][nb][1] + b2.y;
            float v2 = acc[mb][nb][2] + b2.x, v3 = acc[mb][nb][3] + b2.y;
            size_t r0 = (size_t)(j0 + iw + mb * 16 + gi) * DD + dg;
            *(float2*)&g_T[r0]          = make_float2(v0, v1);
            *(float2*)&g_T[r0 + 8 * DD] = make_float2(v2, v3);
            *(uint32_t*)&g_Tbf[r0]          = bf2u(v0, v1);
            *(uint32_t*)&g_Tbf[r0 + 8 * DD] = bf2u(v2, v3);
        }
}

// ================= kernel 4: big GEMM, merged d (128i x 256d per CTA) =================
// 512 threads = 16 warps (4i x 4d). M tile converted once per i-tile; T tile via
// cp.async. grid = 148 = 20 tiles x 3 k-pieces + 44 tiles x 2 k-pieces.
static constexpr int PITCH = 136;                       // sW pitch (128 i + 8)
static constexpr int TP    = 264;                       // sT pitch (256 d + 8)
static constexpr uint32_t SW_BYTES = 32 * PITCH * 2;    // 8704
static constexpr uint32_t ST_BYTES = 32 * TP * 2;       // 16896
static constexpr uint32_t SMEM_DYN = 2 * SW_BYTES + 2 * ST_BYTES;  // 51200

__global__ void __launch_bounds__(512, 1) mma_kernel(const float* __restrict__ M) {
    extern __shared__ __nv_bfloat16 ds[];
    __nv_bfloat16* sW[2] = { ds,                  ds + SW_BYTES / 2 };
    __nv_bfloat16* sT[2] = { ds + SW_BYTES,       ds + SW_BYTES + ST_BYTES / 2 };

    int tid = threadIdx.x;
    int bid = blockIdx.x;

    int tile, part, nparts, cbeg, NC;
    if (bid < 60) {
        tile = bid / 3; part = bid % 3; nparts = 3;
        cbeg = (part == 0) ? 0 : (86 + 85 * (part - 1));
        NC   = (part == 0) ? 86 : 85;
    } else {
        int b2 = bid - 60;
        tile = 20 + (b2 >> 1); part = b2 & 1; nparts = 2;
        cbeg = part * 128; NC = 128;
    }
    int i0 = tile * 128;

    // producer mapping: thread -> (j row cj, 8 i cols ci)
    int cj = tid >> 4, ci = (tid & 15) * 8;
    float4 invA = *(const float4*)&g_inv[i0 + ci];
    float4 invB = *(const float4*)&g_inv[i0 + ci + 4];
    float wa[8] = {};

    // warp/MMA mapping: 16 warps = 4 (i) x 4 (d)
    int w = tid >> 5, lane = tid & 31;
    int iw = (w & 3) * 32, dw = (w >> 2) * 64;
    int q  = lane >> 3, r7 = lane & 7;

    float acc[2][8][4] = {};

    const float*         Mb = M     + (size_t)cbeg * 32 * NN;
    const __nv_bfloat16* Tb = g_Tbf + (size_t)cbeg * 32 * DD;

    float4 mr0, mr1;

    auto LOADM = [&](int c) {
        size_t row = (size_t)c * 32 + cj;
        mr0 = *(const float4*)&Mb[row * NN + i0 + ci];
        mr1 = *(const float4*)&Mb[row * NN + i0 + ci + 4];
    };
    auto ISSUET = [&](int c, int b) {
        size_t row = (size_t)c * 32 + cj;
        uint32_t dst = smem_u32(sT[b]) + (uint32_t)(cj * TP + ci * 2) * 2;
        cp16(dst,      &Tb[row * DD + ci * 2]);
        cp16(dst + 16, &Tb[row * DD + ci * 2 + 8]);
        asm volatile("cp.async.commit_group;" ::: "memory");
    };
    auto STOREM = [&](int b) {
        float w0 = mr0.x * invA.x; w0 = (w0 > THR) ? w0 : 0.f; wa[0] += w0;
        float w1 = mr0.y * invA.y; w1 = (w1 > THR) ? w1 : 0.f; wa[1] += w1;
        float w2 = mr0.z * invA.z; w2 = (w2 > THR) ? w2 : 0.f; wa[2] += w2;
        float w3 = mr0.w * invA.w; w3 = (w3 > THR) ? w3 : 0.f; wa[3] += w3;
        float w4 = mr1.x * invB.x; w4 = (w4 > THR) ? w4 : 0.f; wa[4] += w4;
        float w5 = mr1.y * invB.y; w5 = (w5 > THR) ? w5 : 0.f; wa[5] += w5;
        float w6 = mr1.z * invB.z; w6 = (w6 > THR) ? w6 : 0.f; wa[6] += w6;
        float w7 = mr1.w * invB.w; w7 = (w7 > THR) ? w7 : 0.f; wa[7] += w7;
        uint4 u;
        u.x = bf2u(w0, w1); u.y = bf2u(w2, w3);
        u.z = bf2u(w4, w5); u.w = bf2u(w6, w7);
        *(uint4*)&sW[b][cj * PITCH + ci] = u;
    };

    // prologue: chunk 0
    LOADM(0);
    ISSUET(0, 0);
    STOREM(0);
    asm volatile("cp.async.wait_group 0;" ::: "memory");
    __syncthreads();

    int buf = 0;
    for (int c = 0; c < NC; c++) {
        int nbuf = buf ^ 1;
        if (c + 1 < NC) {
            LOADM(c + 1);
            ISSUET(c + 1, nbuf);
        }

        uint32_t swb = smem_u32(sW[buf]), stb = smem_u32(sT[buf]);
#pragma unroll
        for (int kk = 0; kk < 32; kk += 16) {
            uint32_t a[2][4];
#pragma unroll
            for (int mb = 0; mb < 2; mb++)
                ldsm4t(a[mb], swb + (uint32_t)(((kk + (q >> 1) * 8 + r7) * PITCH + iw + mb * 16 + (q & 1) * 8) * 2));
#pragma unroll
            for (int nbp = 0; nbp < 4; nbp++) {
                uint32_t b[4];
                ldsm4t(b, stb + (uint32_t)(((kk + (q & 1) * 8 + r7) * TP + dw + (nbp * 2 + (q >> 1)) * 8) * 2));
                mma_bf16(acc[0][2 * nbp],     a[0], b);
                mma_bf16(acc[1][2 * nbp],     a[1], b);
                mma_bf16(acc[0][2 * nbp + 1], a[0], b + 2);
                mma_bf16(acc[1][2 * nbp + 1], a[1], b + 2);
            }
        }

        if (c + 1 < NC) {
            STOREM(nbuf);
            asm volatile("cp.async.wait_group 0;" ::: "memory");
        }
        __syncthreads();
        buf = nbuf;
    }

#pragma unroll
    for (int p = 0; p < 8; p++)
        atomicAdd(&g_wsum[i0 + ci + p], wa[p]);

    float* numOut = (part == 0) ? g_numA : (part == 1) ? g_numB : g_numC;
    int gi = lane >> 2, gk = (lane & 3) * 2;
#pragma unroll
    for (int mb = 0; mb < 2; mb++)
#pragma unroll
        for (int nb = 0; nb < 8; nb++) {
            int i = i0 + iw + mb * 16 + gi;
            int d = dw + nb * 8 + gk;
            float* p = &numOut[(size_t)i * DD + d];
            p[0]          = acc[mb][nb][0];
            p[1]          = acc[mb][nb][1];
            p[8 * DD]     = acc[mb][nb][2];
            p[8 * DD + 1] = acc[mb][nb][3];
        }

    if (nparts == 2 && part == 0) {
        for (int idx = tid; idx < 128 * 64; idx += 512) {
            int r = idx >> 6, c4 = (idx & 63) * 4;
            *(float4*)&g_numC[(size_t)(i0 + r) * DD + c4] = make_float4(0.f, 0.f, 0.f, 0.f);
        }
    }
}

// ================= kernel 5: epilogue =================
static constexpr int EBP = 264;

__global__ void __launch_bounds__(256, 1) epi_kernel(const float* __restrict__ X,
                                                     const float* __restrict__ b_out,
                                                     const float* __restrict__ ln_s,
                                                     const float* __restrict__ ln_b,
                                                     float* __restrict__ out) {
    __shared__ __nv_bfloat16 sA[2][64 * AP];
    __shared__ __nv_bfloat16 sB[2][32 * EBP];
    __shared__ float2 red[64][2];
    __shared__ float  winv_s[64];
    __shared__ int    flag_s[64];

    int tid = threadIdx.x;
    int i0  = blockIdx.x * 64;

    if (tid < 64) {
        float ws = g_wsum[i0 + tid];
        winv_s[tid] = 1.f / (ws + EPS);
        flag_s[tid] = (ws > 0.f) ? 1 : 0;
    }
    __syncthreads();

    int ar = tid >> 2, ac = (tid & 3) * 8;
    float wv = winv_s[ar];
    int   fl = flag_s[ar];
    int wk = tid >> 3, wd = (tid & 7) * 32;

    int w = tid >> 5, lane = tid & 31;
    int iwp = (w & 3) * 16, dwp = (w >> 2) * 128;
    int q  = lane >> 3, r7 = lane & 7;
    int l15 = lane & 15, lh = (lane >> 4) * 8;

    float acc[16][4] = {};
    float4 av[2];
    uint4  wr[4];

    auto loadA = [&](int k0, float4* v) {
        size_t base = (size_t)(i0 + ar) * DD + k0 + ac;
        if (fl) {
#pragma unroll
            for (int p = 0; p < 2; p++) {
                float4 a4 = *(const float4*)&g_numA[base + p * 4];
                float4 b4 = *(const float4*)&g_numB[base + p * 4];
                float4 c4 = *(const float4*)&g_numC[base + p * 4];
                v[p] = make_float4((a4.x + b4.x + c4.x) * wv, (a4.y + b4.y + c4.y) * wv,
                                   (a4.z + b4.z + c4.z) * wv, (a4.w + b4.w + c4.w) * wv);
            }
        } else {
#pragma unroll
            for (int p = 0; p < 2; p++) v[p] = *(const float4*)&g_T[base + p * 4];
        }
    };

    loadA(0, av);
#pragma unroll
    for (int p = 0; p < 4; p++)
        wr[p] = *(const uint4*)&g_Woutb[(size_t)wk * DD + wd + p * 8];

    *(uint4*)&sA[0][ar * AP + ac] = cvt8bf(av[0], av[1]);
#pragma unroll
    for (int p = 0; p < 4; p++) *(uint4*)&sB[0][wk * EBP + wd + p * 8] = wr[p];
    __syncthreads();

    const int NCk = DD / 32;
    int buf = 0;
    for (int c = 0; c < NCk; c++) {
        int nbuf = buf ^ 1;
        if (c + 1 < NCk) {
            int k0 = (c + 1) * 32;
            loadA(k0, av);
#pragma unroll
            for (int p = 0; p < 4; p++)
                wr[p] = *(const uint4*)&g_Woutb[(size_t)(k0 + wk) * DD + wd + p * 8];
        }
        uint32_t swb = smem_u32(sA[buf]), stb = smem_u32(sB[buf]);
#pragma unroll
        for (int kk = 0; kk < 32; kk += 16) {
            uint32_t a[4];
            ldsm4(a, swb + (uint32_t)(((iwp + l15) * AP + kk + lh) * 2));
#pragma unroll
            for (int nbp = 0; nbp < 8; nbp++) {
                uint32_t b[4];
                ldsm4t(b, stb + (uint32_t)(((kk + (q & 1) * 8 + r7) * EBP + dwp + (nbp * 2 + (q >> 1)) * 8) * 2));
                mma_bf16(acc[2 * nbp],     a, b);
                mma_bf16(acc[2 * nbp + 1], a, b + 2);
            }
        }
        if (c + 1 < NCk) {
            *(uint4*)&sA[nbuf][ar * AP + ac] = cvt8bf(av[0], av[1]);
#pragma unroll
            for (int p = 0; p < 4; p++) *(uint4*)&sB[nbuf][wk * EBP + wd + p * 8] = wr[p];
        }
        __syncthreads();
        buf = nbuf;
    }

    int gi = lane >> 2, gk = (lane & 3) * 2;
    int r0 = iwp + gi, r1 = r0 + 8;
    float s0 = 0.f, q0 = 0.f, s1 = 0.f, q1 = 0.f;
#pragma unroll
    for (int nb = 0; nb < 16; nb++) {
        int d = dwp + nb * 8 + gk;
        float2 b2 = *(const float2*)&b_out[d];
        float2 x0 = *(const float2*)&X[(size_t)(i0 + r0) * DD + d];
        float2 x1 = *(const float2*)&X[(size_t)(i0 + r1) * DD + d];
        acc[nb][0] += b2.x + x0.x; acc[nb][1] += b2.y + x0.y;
        acc[nb][2] += b2.x + x1.x; acc[nb][3] += b2.y + x1.y;
        s0 += acc[nb][0] + acc[nb][1]; q0 += acc[nb][0] * acc[nb][0] + acc[nb][1] * acc[nb][1];
        s1 += acc[nb][2] + acc[nb][3]; q1 += acc[nb][2] * acc[nb][2] + acc[nb][3] * acc[nb][3];
    }
#pragma unroll
    for (int o = 1; o <= 2; o <<= 1) {
        s0 += __shfl_xor_sync(0xFFFFFFFFu, s0, o);
        q0 += __shfl_xor_sync(0xFFFFFFFFu, q0, o);
        s1 += __shfl_xor_sync(0xFFFFFFFFu, s1, o);
        q1 += __shfl_xor_sync(0xFFFFFFFFu, q1, o);
    }
    int dwi = w >> 2;
    if (gk == 0) {
        red[r0][dwi] = make_float2(s0, q0);
        red[r1][dwi] = make_float2(s1, q1);
    }
    __syncthreads();
    float2 ra0 = red[r0][0], rb0 = red[r0][1];
    float2 ra1 = red[r1][0], rb1 = red[r1][1];
    float mu0 = (ra0.x + rb0.x) * (1.f / 256.f);
    float mu1 = (ra1.x + rb1.x) * (1.f / 256.f);
    float v0  = (ra0.y + rb0.y) * (1.f / 256.f) - mu0 * mu0;
    float v1  = (ra1.y + rb1.y) * (1.f / 256.f) - mu1 * mu1;
    float rs0 = rsqrtf(v0 + LN_EPS), rs1 = rsqrtf(v1 + LN_EPS);
#pragma unroll
    for (int nb = 0; nb < 16; nb++) {
        int d = dwp + nb * 8 + gk;
        float2 ls = *(const float2*)&ln_s[d];
        float2 lb = *(const float2*)&ln_b[d];
        *(float2*)&out[(size_t)(i0 + r0) * DD + d] =
            make_float2((acc[nb][0] - mu0) * rs0 * ls.x + lb.x,
                        (acc[nb][1] - mu0) * rs0 * ls.y + lb.y);
        *(float2*)&out[(size_t)(i0 + r1) * DD + d] =
            make_float2((acc[nb][2] - mu1) * rs1 * ls.x + lb.x,
                        (acc[nb][3] - mu1) * rs1 * ls.y + lb.y);
    }
}

// ================= launch =================
extern "C" void kernel_launch(void* const* d_in, const int* in_sizes, int n_in,
                              void* d_out, int out_size) {
    const float* X     = (const float*)d_in[0];
    const float* M     = (const float*)d_in[1];
    const float* W_in  = (const float*)d_in[2];
    const float* b_in  = (const float*)d_in[3];
    const float* W_out = (const float*)d_in[4];
    const float* b_out = (const float*)d_in[5];
    const float* ln_s  = (const float*)d_in[6];
    const float* ln_b  = (const float*)d_in[7];
    float* out = (float*)d_out;

    cudaFuncSetAttribute(mma_kernel, cudaFuncAttributeMaxDynamicSharedMemorySize, SMEM_DYN);

    colsum_kernel<<<128, 256>>>(M);
    prep_kernel  <<<256, 256>>>(W_in, W_out);
    t_kernel     <<<128, 256>>>(X, b_in);
    mma_kernel   <<<148, 512, SMEM_DYN>>>(M);
    epi_kernel   <<<128, 256>>>(X, b_out, ln_s, ln_b, out);
}

// round 12
// speedup vs baseline: 1.0871x; 1.0871x over previous
#include <cuda_runtime.h>
#include <cuda_bf16.h>
#include <cstdint>

#define DI __device__ __forceinline__

static constexpr int   NN     = 8192;
static constexpr int   DD     = 256;
static constexpr float EPS    = 1e-8f;
static constexpr float THR    = 1e-6f;
static constexpr float LN_EPS = 1e-5f;

// ---------------- device scratch ----------------
__device__ float          g_part[4 * NN];
__device__ float          g_inv[NN];
__device__ float          g_wsum[NN];
__device__ float          g_T[(size_t)NN * DD];
__device__ __nv_bfloat16  g_Tbf[(size_t)NN * DD];
__device__ __nv_bfloat16  g_Winb[DD * DD];
__device__ __nv_bfloat16  g_Woutb[DD * DD];
__device__ float          g_numA[(size_t)NN * DD];
__device__ float          g_numB[(size_t)NN * DD];
__device__ float          g_numC[(size_t)NN * DD];

// ---------------- helpers ----------------
DI uint32_t smem_u32(const void* p) {
    uint32_t a;
    asm("{ .reg .u64 t; cvta.to.shared.u64 t, %1; cvt.u32.u64 %0, t; }" : "=r"(a) : "l"(p));
    return a;
}
DI void ldsm4t(uint32_t* r, uint32_t addr) {
    asm volatile("ldmatrix.sync.aligned.m8n8.x4.trans.shared.b16 {%0,%1,%2,%3}, [%4];"
        : "=r"(r[0]), "=r"(r[1]), "=r"(r[2]), "=r"(r[3]) : "r"(addr));
}
DI void ldsm4(uint32_t* r, uint32_t addr) {
    asm volatile("ldmatrix.sync.aligned.m8n8.x4.shared.b16 {%0,%1,%2,%3}, [%4];"
        : "=r"(r[0]), "=r"(r[1]), "=r"(r[2]), "=r"(r[3]) : "r"(addr));
}
DI void mma_bf16(float* c, const uint32_t* a, const uint32_t* b) {
    asm volatile(
        "mma.sync.aligned.m16n8k16.row.col.f32.bf16.bf16.f32 "
        "{%0,%1,%2,%3}, {%4,%5,%6,%7}, {%8,%9}, {%0,%1,%2,%3};"
        : "+f"(c[0]), "+f"(c[1]), "+f"(c[2]), "+f"(c[3])
        : "r"(a[0]), "r"(a[1]), "r"(a[2]), "r"(a[3]), "r"(b[0]), "r"(b[1]));
}
DI uint32_t bf2u(float lo, float hi) {
    uint32_t r;
    asm("cvt.rn.bf16x2.f32 %0, %1, %2;" : "=r"(r) : "f"(hi), "f"(lo));
    return r;
}
DI uint4 cvt8bf(float4 a, float4 b) {
    uint4 u;
    u.x = bf2u(a.x, a.y); u.y = bf2u(a.z, a.w);
    u.z = bf2u(b.x, b.y); u.w = bf2u(b.z, b.w);
    return u;
}
DI void cp16(uint32_t smem_dst, const void* gptr) {
    asm volatile("cp.async.cg.shared.global [%0], [%1], 16;" :: "r"(smem_dst), "l"(gptr) : "memory");
}

// ================= kernel 1: column sums of M (4 row-quarters, 256 CTAs) =========
__global__ void colsum_kernel(const float* __restrict__ M) {
    __shared__ float red[8 * 128];
    int tid = threadIdx.x;
    int it = blockIdx.x >> 2, quart = blockIdx.x & 3;
    int i0 = it * 128;
    int rg = tid >> 5, i4 = (tid & 31) * 4;

    float a0 = 0.f, a1 = 0.f, a2 = 0.f, a3 = 0.f;
    int rbeg = quart * 2048 + rg, rend = quart * 2048 + 2048;
    for (int r = rbeg; r < rend; r += 32) {
        float4 m0 = *(const float4*)&M[(size_t)(r     ) * NN + i0 + i4];
        float4 m1 = *(const float4*)&M[(size_t)(r +  8) * NN + i0 + i4];
        float4 m2 = *(const float4*)&M[(size_t)(r + 16) * NN + i0 + i4];
        float4 m3 = *(const float4*)&M[(size_t)(r + 24) * NN + i0 + i4];
        a0 += m0.x + m1.x + m2.x + m3.x;
        a1 += m0.y + m1.y + m2.y + m3.y;
        a2 += m0.z + m1.z + m2.z + m3.z;
        a3 += m0.w + m1.w + m2.w + m3.w;
    }
    red[rg * 128 + i4 + 0] = a0; red[rg * 128 + i4 + 1] = a1;
    red[rg * 128 + i4 + 2] = a2; red[rg * 128 + i4 + 3] = a3;
    __syncthreads();
    if (tid < 128) {
        float s = 0.f;
#pragma unroll
        for (int g = 0; g < 8; g++) s += red[g * 128 + tid];
        g_part[quart * NN + i0 + tid] = s;
    }
}

// ================= kernel 2: prep =================
__global__ void prep_kernel(const float* __restrict__ W_in,
                            const float* __restrict__ W_out) {
    int gid = blockIdx.x * 256 + threadIdx.x;
    if (gid < NN) {
        float s = g_part[gid] + g_part[NN + gid] + g_part[2 * NN + gid] + g_part[3 * NN + gid];
        g_inv[gid]  = 1.f / (s + EPS);
        g_wsum[gid] = 0.f;
    }
    g_Winb[gid]  = __float2bfloat16(W_in[gid]);
    g_Woutb[gid] = __float2bfloat16(W_out[gid]);
}

// ================= kernel 3: T = X @ W_in + b_in =================
static constexpr int AP = 40;
static constexpr int BP = 136;

__global__ void __launch_bounds__(256, 1) t_kernel(const float* __restrict__ X,
                                                   const float* __restrict__ b_in) {
    __shared__ __nv_bfloat16 sA[2][128 * AP];
    __shared__ __nv_bfloat16 sB[2][32 * BP];

    int tid = threadIdx.x;
    int j0 = (blockIdx.x >> 1) * 128;
    int d0 = (blockIdx.x & 1) * 128;

    int xj = tid >> 1, xh = (tid & 1) * 16;
    int wk = tid >> 3, wd = (tid & 7) * 16;

    int w = tid >> 5, lane = tid & 31;
    int iw = (w & 3) * 32, dw = (w >> 2) * 64;
    int q = lane >> 3, r7 = lane & 7;
    int l15 = lane & 15, lh = (lane >> 4) * 8;

    float acc[2][8][4] = {};
    float4 xr[4];
    uint4  wr[2];

#pragma unroll
    for (int p = 0; p < 4; p++)
        xr[p] = *(const float4*)&X[(size_t)(j0 + xj) * DD + xh + p * 4];
#pragma unroll
    for (int p = 0; p < 2; p++)
        wr[p] = *(const uint4*)&g_Winb[(size_t)wk * DD + d0 + wd + p * 8];

    *(uint4*)&sA[0][xj * AP + xh]     = cvt8bf(xr[0], xr[1]);
    *(uint4*)&sA[0][xj * AP + xh + 8] = cvt8bf(xr[2], xr[3]);
    *(uint4*)&sB[0][wk * BP + wd]     = wr[0];
    *(uint4*)&sB[0][wk * BP + wd + 8] = wr[1];
    __syncthreads();

    const int NCk = DD / 32;
    int buf = 0;
    for (int c = 0; c < NCk; c++) {
        int nbuf = buf ^ 1;
        if (c + 1 < NCk) {
            int k0 = (c + 1) * 32;
#pragma unroll
            for (int p = 0; p < 4; p++)
                xr[p] = *(const float4*)&X[(size_t)(j0 + xj) * DD + k0 + xh + p * 4];
#pragma unroll
            for (int p = 0; p < 2; p++)
                wr[p] = *(const uint4*)&g_Winb[(size_t)(k0 + wk) * DD + d0 + wd + p * 8];
        }
        uint32_t swb = smem_u32(sA[buf]), stb = smem_u32(sB[buf]);
#pragma unroll
        for (int kk = 0; kk < 32; kk += 16) {
            uint32_t a[2][4];
#pragma unroll
            for (int mb = 0; mb < 2; mb++)
                ldsm4(a[mb], swb + (uint32_t)(((iw + mb * 16 + l15) * AP + kk + lh) * 2));
#pragma unroll
            for (int nbp = 0; nbp < 4; nbp++) {
                uint32_t b[4];
                ldsm4t(b, stb + (uint32_t)(((kk + (q & 1) * 8 + r7) * BP + dw + (nbp * 2 + (q >> 1)) * 8) * 2));
                mma_bf16(acc[0][2 * nbp],     a[0], b);
                mma_bf16(acc[1][2 * nbp],     a[1], b);
                mma_bf16(acc[0][2 * nbp + 1], a[0], b + 2);
                mma_bf16(acc[1][2 * nbp + 1], a[1], b + 2);
            }
        }
        if (c + 1 < NCk) {
            *(uint4*)&sA[nbuf][xj * AP + xh]     = cvt8bf(xr[0], xr[1]);
            *(uint4*)&sA[nbuf][xj * AP + xh + 8] = cvt8bf(xr[2], xr[3]);
            *(uint4*)&sB[nbuf][wk * BP + wd]     = wr[0];
            *(uint4*)&sB[nbuf][wk * BP + wd + 8] = wr[1];
        }
        __syncthreads();
        buf = nbuf;
    }

    int gi = lane >> 2, gk = (lane & 3) * 2;
#pragma unroll
    for (int mb = 0; mb < 2; mb++)
#pragma unroll
        for (int nb = 0; nb < 8; nb++) {
            int dg = d0 + dw + nb * 8 + gk;
            float2 b2 = *(const float2*)&b_in[dg];
            float v0 = acc[mb][nb][0] + b2.x, v1 = acc[mb][nb][1] + b2.y;
            float v2 = acc[mb][nb][2] + b2.x, v3 = acc[mb][nb][3] + b2.y;
            size_t r0 = (size_t)(j0 + iw + mb * 16 + gi) * DD + dg;
            *(float2*)&g_T[r0]          = make_float2(v0, v1);
            *(float2*)&g_T[r0 + 8 * DD] = make_float2(v2, v3);
            *(uint32_t*)&g_Tbf[r0]          = bf2u(v0, v1);
            *(uint32_t*)&g_Tbf[r0 + 8 * DD] = bf2u(v2, v3);
        }
}

// ================= kernel 4: big GEMM, merged d + distance-2 pipeline =================
// 512 threads = 16 warps (4i x 4d), 128i x 256d per CTA, 3-buffer ring,
// M prefetched 2 chunks ahead (register sets), T via cp.async 2 chunks ahead.
static constexpr int PITCH = 136;
static constexpr int TP    = 264;
static constexpr uint32_t SWB = 32 * PITCH * 2;   // 8704 B
static constexpr uint32_t STB = 32 * TP * 2;      // 16896 B
static constexpr uint32_t SMEM_DYN = 3 * SWB + 3 * STB;  // 76800 B

__global__ void __launch_bounds__(512, 1) mma_kernel(const float* __restrict__ M) {
    extern __shared__ __nv_bfloat16 ds[];
    __nv_bfloat16* sW[3] = { ds, ds + SWB / 2, ds + SWB };
    __nv_bfloat16* sT[3] = { ds + 3 * (SWB / 2),
                             ds + 3 * (SWB / 2) + STB / 2,
                             ds + 3 * (SWB / 2) + STB };

    int tid = threadIdx.x;
    int bid = blockIdx.x;

    int tile, part, nparts, cbeg, NC;
    if (bid < 60) {
        tile = bid / 3; part = bid % 3; nparts = 3;
        cbeg = (part == 0) ? 0 : (86 + 85 * (part - 1));
        NC   = (part == 0) ? 86 : 85;
    } else {
        int b2 = bid - 60;
        tile = 20 + (b2 >> 1); part = b2 & 1; nparts = 2;
        cbeg = part * 128; NC = 128;
    }
    int i0 = tile * 128;

    int cj = tid >> 4, ci = (tid & 15) * 8;
    float4 invA = *(const float4*)&g_inv[i0 + ci];
    float4 invB = *(const float4*)&g_inv[i0 + ci + 4];
    float wa[8] = {};

    int w = tid >> 5, lane = tid & 31;
    int iw = (w & 3) * 32, dw = (w >> 2) * 64;
    int q  = lane >> 3, r7 = lane & 7;

    float acc[2][8][4] = {};

    const float*         Mb = M     + (size_t)cbeg * 32 * NN;
    const __nv_bfloat16* Tb = g_Tbf + (size_t)cbeg * 32 * DD;

    float4 mA0, mA1, mB0, mB1;

    auto LOADM = [&](int c, float4& a, float4& b) {
        size_t row = (size_t)c * 32 + cj;
        a = *(const float4*)&Mb[row * NN + i0 + ci];
        b = *(const float4*)&Mb[row * NN + i0 + ci + 4];
    };
    auto ISSUET = [&](int c) {
        int b = c % 3;
        size_t row = (size_t)c * 32 + cj;
        uint32_t dst = smem_u32(sT[b]) + (uint32_t)(cj * TP + ci * 2) * 2;
        cp16(dst,      &Tb[row * DD + ci * 2]);
        cp16(dst + 16, &Tb[row * DD + ci * 2 + 8]);
        asm volatile("cp.async.commit_group;" ::: "memory");
    };
    auto STOREM = [&](float4 m0, float4 m1, int b) {
        float w0 = m0.x * invA.x; w0 = (w0 > THR) ? w0 : 0.f; wa[0] += w0;
        float w1 = m0.y * invA.y; w1 = (w1 > THR) ? w1 : 0.f; wa[1] += w1;
        float w2 = m0.z * invA.z; w2 = (w2 > THR) ? w2 : 0.f; wa[2] += w2;
        float w3 = m0.w * invA.w; w3 = (w3 > THR) ? w3 : 0.f; wa[3] += w3;
        float w4 = m1.x * invB.x; w4 = (w4 > THR) ? w4 : 0.f; wa[4] += w4;
        float w5 = m1.y * invB.y; w5 = (w5 > THR) ? w5 : 0.f; wa[5] += w5;
        float w6 = m1.z * invB.z; w6 = (w6 > THR) ? w6 : 0.f; wa[6] += w6;
        float w7 = m1.w * invB.w; w7 = (w7 > THR) ? w7 : 0.f; wa[7] += w7;
        uint4 u;
        u.x = bf2u(w0, w1); u.y = bf2u(w2, w3);
        u.z = bf2u(w4, w5); u.w = bf2u(w6, w7);
        *(uint4*)&sW[b][cj * PITCH + ci] = u;
    };

    // prologue: chunks 0 and 1
    LOADM(0, mA0, mA1);
    ISSUET(0);
    LOADM(1, mB0, mB1);
    ISSUET(1);
    STOREM(mA0, mA1, 0);
    asm volatile("cp.async.wait_group 1;" ::: "memory");   // T0 done, T1 in flight
    __syncthreads();
    mA0 = mB0; mA1 = mB1;                                  // mA holds chunk 1

    for (int c = 0; c < NC; c++) {
        int r = c % 3;
        if (c + 2 < NC) {
            LOADM(c + 2, mB0, mB1);
            ISSUET(c + 2);
        }

        uint32_t swb = smem_u32(sW[r]), stb = smem_u32(sT[r]);
#pragma unroll
        for (int kk = 0; kk < 32; kk += 16) {
            uint32_t a[2][4];
#pragma unroll
            for (int mb = 0; mb < 2; mb++)
                ldsm4t(a[mb], swb + (uint32_t)(((kk + (q >> 1) * 8 + r7) * PITCH + iw + mb * 16 + (q & 1) * 8) * 2));
#pragma unroll
            for (int nbp = 0; nbp < 4; nbp++) {
                uint32_t b[4];
                ldsm4t(b, stb + (uint32_t)(((kk + (q & 1) * 8 + r7) * TP + dw + (nbp * 2 + (q >> 1)) * 8) * 2));
                mma_bf16(acc[0][2 * nbp],     a[0], b);
                mma_bf16(acc[1][2 * nbp],     a[1], b);
                mma_bf16(acc[0][2 * nbp + 1], a[0], b + 2);
                mma_bf16(acc[1][2 * nbp + 1], a[1], b + 2);
            }
        }

        if (c + 1 < NC) STOREM(mA0, mA1, (c + 1) % 3);
        if (c + 2 < NC) { asm volatile("cp.async.wait_group 1;" ::: "memory"); }
        else            { asm volatile("cp.async.wait_group 0;" ::: "memory"); }
        __syncthreads();
        mA0 = mB0; mA1 = mB1;
    }

#pragma unroll
    for (int p = 0; p < 8; p++)
        atomicAdd(&g_wsum[i0 + ci + p], wa[p]);

    float* numOut = (part == 0) ? g_numA : (part == 1) ? g_numB : g_numC;
    int gi = lane >> 2, gk = (lane & 3) * 2;
#pragma unroll
    for (int mb = 0; mb < 2; mb++)
#pragma unroll
        for (int nb = 0; nb < 8; nb++) {
            int i = i0 + iw + mb * 16 + gi;
            int d = dw + nb * 8 + gk;
            float* p = &numOut[(size_t)i * DD + d];
            p[0]          = acc[mb][nb][0];
            p[1]          = acc[mb][nb][1];
            p[8 * DD]     = acc[mb][nb][2];
            p[8 * DD + 1] = acc[mb][nb][3];
        }

    if (nparts == 2 && part == 0) {
        for (int idx = tid; idx < 128 * 64; idx += 512) {
            int r = idx >> 6, c4 = (idx & 63) * 4;
            *(float4*)&g_numC[(size_t)(i0 + r) * DD + c4] = make_float4(0.f, 0.f, 0.f, 0.f);
        }
    }
}

// ================= kernel 5: epilogue =================
static constexpr int EBP = 264;

__global__ void __launch_bounds__(256, 1) epi_kernel(const float* __restrict__ X,
                                                     const float* __restrict__ b_out,
                                                     const float* __restrict__ ln_s,
                                                     const float* __restrict__ ln_b,
                                                     float* __restrict__ out) {
    __shared__ __nv_bfloat16 sA[2][64 * AP];
    __shared__ __nv_bfloat16 sB[2][32 * EBP];
    __shared__ float2 red[64][2];
    __shared__ float  winv_s[64];
    __shared__ int    flag_s[64];

    int tid = threadIdx.x;
    int i0  = blockIdx.x * 64;

    if (tid < 64) {
        float ws = g_wsum[i0 + tid];
        winv_s[tid] = 1.f / (ws + EPS);
        flag_s[tid] = (ws > 0.f) ? 1 : 0;
    }
    __syncthreads();

    int ar = tid >> 2, ac = (tid & 3) * 8;
    float wv = winv_s[ar];
    int   fl = flag_s[ar];
    int wk = tid >> 3, wd = (tid & 7) * 32;

    int w = tid >> 5, lane = tid & 31;
    int iwp = (w & 3) * 16, dwp = (w >> 2) * 128;
    int q  = lane >> 3, r7 = lane & 7;
    int l15 = lane & 15, lh = (lane >> 4) * 8;

    float acc[16][4] = {};
    float4 av[2];
    uint4  wr[4];

    auto loadA = [&](int k0, float4* v) {
        size_t base = (size_t)(i0 + ar) * DD + k0 + ac;
        if (fl) {
#pragma unroll
            for (int p = 0; p < 2; p++) {
                float4 a4 = *(const float4*)&g_numA[base + p * 4];
                float4 b4 = *(const float4*)&g_numB[base + p * 4];
                float4 c4 = *(const float4*)&g_numC[base + p * 4];
                v[p] = make_float4((a4.x + b4.x + c4.x) * wv, (a4.y + b4.y + c4.y) * wv,
                                   (a4.z + b4.z + c4.z) * wv, (a4.w + b4.w + c4.w) * wv);
            }
        } else {
#pragma unroll
            for (int p = 0; p < 2; p++) v[p] = *(const float4*)&g_T[base + p * 4];
        }
    };

    loadA(0, av);
#pragma unroll
    for (int p = 0; p < 4; p++)
        wr[p] = *(const uint4*)&g_Woutb[(size_t)wk * DD + wd + p * 8];

    *(uint4*)&sA[0][ar * AP + ac] = cvt8bf(av[0], av[1]);
#pragma unroll
    for (int p = 0; p < 4; p++) *(uint4*)&sB[0][wk * EBP + wd + p * 8] = wr[p];
    __syncthreads();

    const int NCk = DD / 32;
    int buf = 0;
    for (int c = 0; c < NCk; c++) {
        int nbuf = buf ^ 1;
        if (c + 1 < NCk) {
            int k0 = (c + 1) * 32;
            loadA(k0, av);
#pragma unroll
            for (int p = 0; p < 4; p++)
                wr[p] = *(const uint4*)&g_Woutb[(size_t)(k0 + wk) * DD + wd + p * 8];
        }
        uint32_t swb = smem_u32(sA[buf]), stb = smem_u32(sB[buf]);
#pragma unroll
        for (int kk = 0; kk < 32; kk += 16) {
            uint32_t a[4];
            ldsm4(a, swb + (uint32_t)(((iwp + l15) * AP + kk + lh) * 2));
#pragma unroll
            for (int nbp = 0; nbp < 8; nbp++) {
                uint32_t b[4];
                ldsm4t(b, stb + (uint32_t)(((kk + (q & 1) * 8 + r7) * EBP + dwp + (nbp * 2 + (q >> 1)) * 8) * 2));
                mma_bf16(acc[2 * nbp],     a, b);
                mma_bf16(acc[2 * nbp + 1], a, b + 2);
            }
        }
        if (c + 1 < NCk) {
            *(uint4*)&sA[nbuf][ar * AP + ac] = cvt8bf(av[0], av[1]);
#pragma unroll
            for (int p = 0; p < 4; p++) *(uint4*)&sB[nbuf][wk * EBP + wd + p * 8] = wr[p];
        }
        __syncthreads();
        buf = nbuf;
    }

    int gi = lane >> 2, gk = (lane & 3) * 2;
    int r0 = iwp + gi, r1 = r0 + 8;
    float s0 = 0.f, q0 = 0.f, s1 = 0.f, q1 = 0.f;
#pragma unroll
    for (int nb = 0; nb < 16; nb++) {
        int d = dwp + nb * 8 + gk;
        float2 b2 = *(const float2*)&b_out[d];
        float2 x0 = *(const float2*)&X[(size_t)(i0 + r0) * DD + d];
        float2 x1 = *(const float2*)&X[(size_t)(i0 + r1) * DD + d];
        acc[nb][0] += b2.x + x0.x; acc[nb][1] += b2.y + x0.y;
        acc[nb][2] += b2.x + x1.x; acc[nb][3] += b2.y + x1.y;
        s0 += acc[nb][0] + acc[nb][1]; q0 += acc[nb][0] * acc[nb][0] + acc[nb][1] * acc[nb][1];
        s1 += acc[nb][2] + acc[nb][3]; q1 += acc[nb][2] * acc[nb][2] + acc[nb][3] * acc[nb][3];
    }
#pragma unroll
    for (int o = 1; o <= 2; o <<= 1) {
        s0 += __shfl_xor_sync(0xFFFFFFFFu, s0, o);
        q0 += __shfl_xor_sync(0xFFFFFFFFu, q0, o);
        s1 += __shfl_xor_sync(0xFFFFFFFFu, s1, o);
        q1 += __shfl_xor_sync(0xFFFFFFFFu, q1, o);
    }
    int dwi = w >> 2;
    if (gk == 0) {
        red[r0][dwi] = make_float2(s0, q0);
        red[r1][dwi] = make_float2(s1, q1);
    }
    __syncthreads();
    float2 ra0 = red[r0][0], rb0 = red[r0][1];
    float2 ra1 = red[r1][0], rb1 = red[r1][1];
    float mu0 = (ra0.x + rb0.x) * (1.f / 256.f);
    float mu1 = (ra1.x + rb1.x) * (1.f / 256.f);
    float v0  = (ra0.y + rb0.y) * (1.f / 256.f) - mu0 * mu0;
    float v1  = (ra1.y + rb1.y) * (1.f / 256.f) - mu1 * mu1;
    float rs0 = rsqrtf(v0 + LN_EPS), rs1 = rsqrtf(v1 + LN_EPS);
#pragma unroll
    for (int nb = 0; nb < 16; nb++) {
        int d = dwp + nb * 8 + gk;
        float2 ls = *(const float2*)&ln_s[d];
        float2 lb = *(const float2*)&ln_b[d];
        *(float2*)&out[(size_t)(i0 + r0) * DD + d] =
            make_float2((acc[nb][0] - mu0) * rs0 * ls.x + lb.x,
                        (acc[nb][1] - mu0) * rs0 * ls.y + lb.y);
        *(float2*)&out[(size_t)(i0 + r1) * DD + d] =
            make_float2((acc[nb][2] - mu1) * rs1 * ls.x + lb.x,
                        (acc[nb][3] - mu1) * rs1 * ls.y + lb.y);
    }
}

// ================= launch =================
extern "C" void kernel_launch(void* const* d_in, const int* in_sizes, int n_in,
                              void* d_out, int out_size) {
    const float* X     = (const float*)d_in[0];
    const float* M     = (const float*)d_in[1];
    const float* W_in  = (const float*)d_in[2];
    const float* b_in  = (const float*)d_in[3];
    const float* W_out = (const float*)d_in[4];
    const float* b_out = (const float*)d_in[5];
    const float* ln_s  = (const float*)d_in[6];
    const float* ln_b  = (const float*)d_in[7];
    float* out = (float*)d_out;

    cudaFuncSetAttribute(mma_kernel, cudaFuncAttributeMaxDynamicSharedMemorySize, SMEM_DYN);

    colsum_kernel<<<256, 256>>>(M);
    prep_kernel  <<<256, 256>>>(W_in, W_out);
    t_kernel     <<<128, 256>>>(X, b_in);
    mma_kernel   <<<148, 512, SMEM_DYN>>>(M);
    epi_kernel   <<<128, 256>>>(X, b_out, ln_s, ln_b, out);
}

// round 13
// speedup vs baseline: 1.2155x; 1.1181x over previous
#include <cuda_runtime.h>
#include <cuda_bf16.h>
#include <cstdint>

#define DI __device__ __forceinline__

static constexpr int   NN     = 8192;
static constexpr int   DD     = 256;
static constexpr float EPS    = 1e-8f;
static constexpr float THR    = 1e-6f;
static constexpr float LN_EPS = 1e-5f;

// ---------------- device scratch ----------------
__device__ float          g_part[4 * NN];
__device__ float          g_inv[NN];
__device__ float          g_wsum[NN];
__device__ float          g_T[(size_t)NN * DD];
__device__ __nv_bfloat16  g_Tbf[(size_t)NN * DD];
__device__ __nv_bfloat16  g_Winb[DD * DD];
__device__ __nv_bfloat16  g_Woutb[DD * DD];
__device__ float          g_numA[(size_t)NN * DD];
__device__ float          g_numB[(size_t)NN * DD];
__device__ float          g_numC[(size_t)NN * DD];

// ---------------- helpers ----------------
DI uint32_t smem_u32(const void* p) {
    uint32_t a;
    asm("{ .reg .u64 t; cvta.to.shared.u64 t, %1; cvt.u32.u64 %0, t; }" : "=r"(a) : "l"(p));
    return a;
}
DI void ldsm4t(uint32_t* r, uint32_t addr) {
    asm volatile("ldmatrix.sync.aligned.m8n8.x4.trans.shared.b16 {%0,%1,%2,%3}, [%4];"
        : "=r"(r[0]), "=r"(r[1]), "=r"(r[2]), "=r"(r[3]) : "r"(addr));
}
DI void ldsm4(uint32_t* r, uint32_t addr) {
    asm volatile("ldmatrix.sync.aligned.m8n8.x4.shared.b16 {%0,%1,%2,%3}, [%4];"
        : "=r"(r[0]), "=r"(r[1]), "=r"(r[2]), "=r"(r[3]) : "r"(addr));
}
DI void mma_bf16(float* c, const uint32_t* a, const uint32_t* b) {
    asm volatile(
        "mma.sync.aligned.m16n8k16.row.col.f32.bf16.bf16.f32 "
        "{%0,%1,%2,%3}, {%4,%5,%6,%7}, {%8,%9}, {%0,%1,%2,%3};"
        : "+f"(c[0]), "+f"(c[1]), "+f"(c[2]), "+f"(c[3])
        : "r"(a[0]), "r"(a[1]), "r"(a[2]), "r"(a[3]), "r"(b[0]), "r"(b[1]));
}
DI uint32_t bf2u(float lo, float hi) {
    uint32_t r;
    asm("cvt.rn.bf16x2.f32 %0, %1, %2;" : "=r"(r) : "f"(hi), "f"(lo));
    return r;
}
DI uint4 cvt8bf(float4 a, float4 b) {
    uint4 u;
    u.x = bf2u(a.x, a.y); u.y = bf2u(a.z, a.w);
    u.z = bf2u(b.x, b.y); u.w = bf2u(b.z, b.w);
    return u;
}

// ================= kernel 1: column sums of M (4 row-quarters, 256 CTAs) =========
__global__ void colsum_kernel(const float* __restrict__ M) {
    __shared__ float red[8 * 128];
    int tid = threadIdx.x;
    int it = blockIdx.x >> 2, quart = blockIdx.x & 3;
    int i0 = it * 128;
    int rg = tid >> 5, i4 = (tid & 31) * 4;

    float a0 = 0.f, a1 = 0.f, a2 = 0.f, a3 = 0.f;
    int rbeg = quart * 2048 + rg, rend = quart * 2048 + 2048;
    for (int r = rbeg; r < rend; r += 32) {
        float4 m0 = *(const float4*)&M[(size_t)(r     ) * NN + i0 + i4];
        float4 m1 = *(const float4*)&M[(size_t)(r +  8) * NN + i0 + i4];
        float4 m2 = *(const float4*)&M[(size_t)(r + 16) * NN + i0 + i4];
        float4 m3 = *(const float4*)&M[(size_t)(r + 24) * NN + i0 + i4];
        a0 += m0.x + m1.x + m2.x + m3.x;
        a1 += m0.y + m1.y + m2.y + m3.y;
        a2 += m0.z + m1.z + m2.z + m3.z;
        a3 += m0.w + m1.w + m2.w + m3.w;
    }
    red[rg * 128 + i4 + 0] = a0; red[rg * 128 + i4 + 1] = a1;
    red[rg * 128 + i4 + 2] = a2; red[rg * 128 + i4 + 3] = a3;
    __syncthreads();
    if (tid < 128) {
        float s = 0.f;
#pragma unroll
        for (int g = 0; g < 8; g++) s += red[g * 128 + tid];
        g_part[quart * NN + i0 + tid] = s;
    }
}

// ================= kernel 2: prep =================
__global__ void prep_kernel(const float* __restrict__ W_in,
                            const float* __restrict__ W_out) {
    int gid = blockIdx.x * 256 + threadIdx.x;
    if (gid < NN) {
        float s = g_part[gid] + g_part[NN + gid] + g_part[2 * NN + gid] + g_part[3 * NN + gid];
        g_inv[gid]  = 1.f / (s + EPS);
        g_wsum[gid] = 0.f;
    }
    g_Winb[gid]  = __float2bfloat16(W_in[gid]);
    g_Woutb[gid] = __float2bfloat16(W_out[gid]);
}

// ================= kernel 3: T = X @ W_in + b_in =================
static constexpr int AP = 40;
static constexpr int BP = 136;

__global__ void __launch_bounds__(256, 1) t_kernel(const float* __restrict__ X,
                                                   const float* __restrict__ b_in) {
    __shared__ __nv_bfloat16 sA[2][128 * AP];
    __shared__ __nv_bfloat16 sB[2][32 * BP];

    int tid = threadIdx.x;
    int j0 = (blockIdx.x >> 1) * 128;
    int d0 = (blockIdx.x & 1) * 128;

    int xj = tid >> 1, xh = (tid & 1) * 16;
    int wk = tid >> 3, wd = (tid & 7) * 16;

    int w = tid >> 5, lane = tid & 31;
    int iw = (w & 3) * 32, dw = (w >> 2) * 64;
    int q = lane >> 3, r7 = lane & 7;
    int l15 = lane & 15, lh = (lane >> 4) * 8;

    float acc[2][8][4] = {};
    float4 xr[4];
    uint4  wr[2];

#pragma unroll
    for (int p = 0; p < 4; p++)
        xr[p] = *(const float4*)&X[(size_t)(j0 + xj) * DD + xh + p * 4];
#pragma unroll
    for (int p = 0; p < 2; p++)
        wr[p] = *(const uint4*)&g_Winb[(size_t)wk * DD + d0 + wd + p * 8];

    *(uint4*)&sA[0][xj * AP + xh]     = cvt8bf(xr[0], xr[1]);
    *(uint4*)&sA[0][xj * AP + xh + 8] = cvt8bf(xr[2], xr[3]);
    *(uint4*)&sB[0][wk * BP + wd]     = wr[0];
    *(uint4*)&sB[0][wk * BP + wd + 8] = wr[1];
    __syncthreads();

    const int NCk = DD / 32;
    int buf = 0;
    for (int c = 0; c < NCk; c++) {
        int nbuf = buf ^ 1;
        if (c + 1 < NCk) {
            int k0 = (c + 1) * 32;
#pragma unroll
            for (int p = 0; p < 4; p++)
                xr[p] = *(const float4*)&X[(size_t)(j0 + xj) * DD + k0 + xh + p * 4];
#pragma unroll
            for (int p = 0; p < 2; p++)
                wr[p] = *(const uint4*)&g_Winb[(size_t)(k0 + wk) * DD + d0 + wd + p * 8];
        }
        uint32_t swb = smem_u32(sA[buf]), stb = smem_u32(sB[buf]);
#pragma unroll
        for (int kk = 0; kk < 32; kk += 16) {
            uint32_t a[2][4];
#pragma unroll
            for (int mb = 0; mb < 2; mb++)
                ldsm4(a[mb], swb + (uint32_t)(((iw + mb * 16 + l15) * AP + kk + lh) * 2));
#pragma unroll
            for (int nbp = 0; nbp < 4; nbp++) {
                uint32_t b[4];
                ldsm4t(b, stb + (uint32_t)(((kk + (q & 1) * 8 + r7) * BP + dw + (nbp * 2 + (q >> 1)) * 8) * 2));
                mma_bf16(acc[0][2 * nbp],     a[0], b);
                mma_bf16(acc[1][2 * nbp],     a[1], b);
                mma_bf16(acc[0][2 * nbp + 1], a[0], b + 2);
                mma_bf16(acc[1][2 * nbp + 1], a[1], b + 2);
            }
        }
        if (c + 1 < NCk) {
            *(uint4*)&sA[nbuf][xj * AP + xh]     = cvt8bf(xr[0], xr[1]);
            *(uint4*)&sA[nbuf][xj * AP + xh + 8] = cvt8bf(xr[2], xr[3]);
            *(uint4*)&sB[nbuf][wk * BP + wd]     = wr[0];
            *(uint4*)&sB[nbuf][wk * BP + wd + 8] = wr[1];
        }
        __syncthreads();
        buf = nbuf;
    }

    int gi = lane >> 2, gk = (lane & 3) * 2;
#pragma unroll
    for (int mb = 0; mb < 2; mb++)
#pragma unroll
        for (int nb = 0; nb < 8; nb++) {
            int dg = d0 + dw + nb * 8 + gk;
            float2 b2 = *(const float2*)&b_in[dg];
            float v0 = acc[mb][nb][0] + b2.x, v1 = acc[mb][nb][1] + b2.y;
            float v2 = acc[mb][nb][2] + b2.x, v3 = acc[mb][nb][3] + b2.y;
            size_t r0 = (size_t)(j0 + iw + mb * 16 + gi) * DD + dg;
            *(float2*)&g_T[r0]          = make_float2(v0, v1);
            *(float2*)&g_T[r0 + 8 * DD] = make_float2(v2, v3);
            *(uint32_t*)&g_Tbf[r0]          = bf2u(v0, v1);
            *(uint32_t*)&g_Tbf[r0 + 8 * DD] = bf2u(v2, v3);
        }
}

// ================= kernel 4: big GEMM (R9 design: 296 CTAs, 2/SM, 128i x 128d) ====
static constexpr int PITCH = 136;

__global__ void __launch_bounds__(256, 2) mma_kernel(const float* __restrict__ M) {
    __shared__ __nv_bfloat16 sW[2][32 * PITCH];
    __shared__ __nv_bfloat16 sT[2][32 * PITCH];

    int tid = threadIdx.x;
    int bid = blockIdx.x;
    // 128 tiles; tiles 0..39 -> 3 pieces (86/85/85 chunks), 40..127 -> 2 (128/128)
    int tile, part, nparts, cbeg, NC;
    if (bid < 120) {
        tile = bid / 3; part = bid % 3; nparts = 3;
        cbeg = (part == 0) ? 0 : (86 + 85 * (part - 1));
        NC   = (part == 0) ? 86 : 85;
    } else {
        int b2 = bid - 120;
        tile = 40 + (b2 >> 1); part = b2 & 1; nparts = 2;
        cbeg = part * 128; NC = 128;
    }
    int it = tile >> 1, dt = tile & 1;
    int i0 = it * 128, d0 = dt * 128;

    int cj = tid >> 5;
    int ci = (tid & 31) * 4;
    float4 inv4 = *(const float4*)&g_inv[i0 + ci];
    float wa0 = 0.f, wa1 = 0.f, wa2 = 0.f, wa3 = 0.f;

    int tj = tid >> 4;
    int tc = (tid & 15) * 8;

    int w = tid >> 5, lane = tid & 31;
    int iw = (w & 3) * 32, dw = (w >> 2) * 64;
    int q  = lane >> 3, r7 = lane & 7;

    float acc[2][8][4] = {};

    const float*          Mb = M     + (size_t)cbeg * 32 * NN;
    const __nv_bfloat16*  Tb = g_Tbf + (size_t)cbeg * 32 * DD;

    float4 mr[4], tr[2];
#pragma unroll
    for (int jj = 0; jj < 4; jj++)
        mr[jj] = *(const float4*)&Mb[(size_t)(cj + jj * 8) * NN + i0 + ci];
#pragma unroll
    for (int jj = 0; jj < 2; jj++)
        tr[jj] = *(const float4*)&Tb[(size_t)(tj + jj * 16) * DD + d0 + tc];

#pragma unroll
    for (int jj = 0; jj < 4; jj++) {
        int j = cj + jj * 8;
        float w0 = mr[jj].x * inv4.x; w0 = (w0 > THR) ? w0 : 0.f;
        float w1 = mr[jj].y * inv4.y; w1 = (w1 > THR) ? w1 : 0.f;
        float w2 = mr[jj].z * inv4.z; w2 = (w2 > THR) ? w2 : 0.f;
        float w3 = mr[jj].w * inv4.w; w3 = (w3 > THR) ? w3 : 0.f;
        if (dt == 0) { wa0 += w0; wa1 += w1; wa2 += w2; wa3 += w3; }
        *(uint32_t*)&sW[0][j * PITCH + ci]     = bf2u(w0, w1);
        *(uint32_t*)&sW[0][j * PITCH + ci + 2] = bf2u(w2, w3);
    }
#pragma unroll
    for (int jj = 0; jj < 2; jj++)
        *(float4*)&sT[0][(tj + jj * 16) * PITCH + tc] = tr[jj];
    __syncthreads();

    int buf = 0;
    for (int c = 0; c < NC; c++) {
        int nbuf = buf ^ 1;
        if (c + 1 < NC) {
            size_t koff = (size_t)(c + 1) * 32;
#pragma unroll
            for (int jj = 0; jj < 4; jj++)
                mr[jj] = *(const float4*)&Mb[(koff + cj + jj * 8) * NN + i0 + ci];
#pragma unroll
            for (int jj = 0; jj < 2; jj++)
                tr[jj] = *(const float4*)&Tb[(koff + tj + jj * 16) * DD + d0 + tc];
        }

        uint32_t swb = smem_u32(sW[buf]), stb = smem_u32(sT[buf]);
#pragma unroll
        for (int kk = 0; kk < 32; kk += 16) {
            uint32_t a[2][4];
#pragma unroll
            for (int mb = 0; mb < 2; mb++)
                ldsm4t(a[mb], swb + (uint32_t)(((kk + (q >> 1) * 8 + r7) * PITCH + iw + mb * 16 + (q & 1) * 8) * 2));
#pragma unroll
            for (int nbp = 0; nbp < 4; nbp++) {
                uint32_t b[4];
                ldsm4t(b, stb + (uint32_t)(((kk + (q & 1) * 8 + r7) * PITCH + dw + (nbp * 2 + (q >> 1)) * 8) * 2));
                mma_bf16(acc[0][2 * nbp],     a[0], b);
                mma_bf16(acc[1][2 * nbp],     a[1], b);
                mma_bf16(acc[0][2 * nbp + 1], a[0], b + 2);
                mma_bf16(acc[1][2 * nbp + 1], a[1], b + 2);
            }
        }

        if (c + 1 < NC) {
#pragma unroll
            for (int jj = 0; jj < 4; jj++) {
                int j = cj + jj * 8;
                float w0 = mr[jj].x * inv4.x; w0 = (w0 > THR) ? w0 : 0.f;
                float w1 = mr[jj].y * inv4.y; w1 = (w1 > THR) ? w1 : 0.f;
                float w2 = mr[jj].z * inv4.z; w2 = (w2 > THR) ? w2 : 0.f;
                float w3 = mr[jj].w * inv4.w; w3 = (w3 > THR) ? w3 : 0.f;
                if (dt == 0) { wa0 += w0; wa1 += w1; wa2 += w2; wa3 += w3; }
                *(uint32_t*)&sW[nbuf][j * PITCH + ci]     = bf2u(w0, w1);
                *(uint32_t*)&sW[nbuf][j * PITCH + ci + 2] = bf2u(w2, w3);
            }
#pragma unroll
            for (int jj = 0; jj < 2; jj++)
                *(float4*)&sT[nbuf][(tj + jj * 16) * PITCH + tc] = tr[jj];
        }
        __syncthreads();
        buf = nbuf;
    }

    if (dt == 0) {
        atomicAdd(&g_wsum[i0 + ci + 0], wa0);
        atomicAdd(&g_wsum[i0 + ci + 1], wa1);
        atomicAdd(&g_wsum[i0 + ci + 2], wa2);
        atomicAdd(&g_wsum[i0 + ci + 3], wa3);
    }

    float* numOut = (part == 0) ? g_numA : (part == 1) ? g_numB : g_numC;
    int gi = lane >> 2, gk = (lane & 3) * 2;
#pragma unroll
    for (int mb = 0; mb < 2; mb++)
#pragma unroll
        for (int nb = 0; nb < 8; nb++) {
            int i = i0 + iw + mb * 16 + gi;
            int d = d0 + dw + nb * 8 + gk;
            float* p = &numOut[(size_t)i * DD + d];
            p[0]          = acc[mb][nb][0];
            p[1]          = acc[mb][nb][1];
            p[8 * DD]     = acc[mb][nb][2];
            p[8 * DD + 1] = acc[mb][nb][3];
        }

    if (nparts == 2 && part == 0) {
        for (int idx = tid; idx < 128 * 32; idx += 256) {
            int r = idx >> 5, c4 = (idx & 31) * 4;
            *(float4*)&g_numC[(size_t)(i0 + r) * DD + d0 + c4] = make_float4(0.f, 0.f, 0.f, 0.f);
        }
    }
}

// ================= kernel 5: epilogue =================
static constexpr int EBP = 264;

__global__ void __launch_bounds__(256, 1) epi_kernel(const float* __restrict__ X,
                                                     const float* __restrict__ b_out,
                                                     const float* __restrict__ ln_s,
                                                     const float* __restrict__ ln_b,
                                                     float* __restrict__ out) {
    __shared__ __nv_bfloat16 sA[2][64 * AP];
    __shared__ __nv_bfloat16 sB[2][32 * EBP];
    __shared__ float2 red[64][2];
    __shared__ float  winv_s[64];
    __shared__ int    flag_s[64];

    int tid = threadIdx.x;
    int i0  = blockIdx.x * 64;

    if (tid < 64) {
        float ws = g_wsum[i0 + tid];
        winv_s[tid] = 1.f / (ws + EPS);
        flag_s[tid] = (ws > 0.f) ? 1 : 0;
    }
    __syncthreads();

    int ar = tid >> 2, ac = (tid & 3) * 8;
    float wv = winv_s[ar];
    int   fl = flag_s[ar];
    int wk = tid >> 3, wd = (tid & 7) * 32;

    int w = tid >> 5, lane = tid & 31;
    int iwp = (w & 3) * 16, dwp = (w >> 2) * 128;
    int q  = lane >> 3, r7 = lane & 7;
    int l15 = lane & 15, lh = (lane >> 4) * 8;

    float acc[16][4] = {};
    float4 av[2];
    uint4  wr[4];

    auto loadA = [&](int k0, float4* v) {
        size_t base = (size_t)(i0 + ar) * DD + k0 + ac;
        if (fl) {
#pragma unroll
            for (int p = 0; p < 2; p++) {
                float4 a4 = *(const float4*)&g_numA[base + p * 4];
                float4 b4 = *(const float4*)&g_numB[base + p * 4];
                float4 c4 = *(const float4*)&g_numC[base + p * 4];
                v[p] = make_float4((a4.x + b4.x + c4.x) * wv, (a4.y + b4.y + c4.y) * wv,
                                   (a4.z + b4.z + c4.z) * wv, (a4.w + b4.w + c4.w) * wv);
            }
        } else {
#pragma unroll
            for (int p = 0; p < 2; p++) v[p] = *(const float4*)&g_T[base + p * 4];
        }
    };

    loadA(0, av);
#pragma unroll
    for (int p = 0; p < 4; p++)
        wr[p] = *(const uint4*)&g_Woutb[(size_t)wk * DD + wd + p * 8];

    *(uint4*)&sA[0][ar * AP + ac] = cvt8bf(av[0], av[1]);
#pragma unroll
    for (int p = 0; p < 4; p++) *(uint4*)&sB[0][wk * EBP + wd + p * 8] = wr[p];
    __syncthreads();

    const int NCk = DD / 32;
    int buf = 0;
    for (int c = 0; c < NCk; c++) {
        int nbuf = buf ^ 1;
        if (c + 1 < NCk) {
            int k0 = (c + 1) * 32;
            loadA(k0, av);
#pragma unroll
            for (int p = 0; p < 4; p++)
                wr[p] = *(const uint4*)&g_Woutb[(size_t)(k0 + wk) * DD + wd + p * 8];
        }
        uint32_t swb = smem_u32(sA[buf]), stb = smem_u32(sB[buf]);
#pragma unroll
        for (int kk = 0; kk < 32; kk += 16) {
            uint32_t a[4];
            ldsm4(a, swb + (uint32_t)(((iwp + l15) * AP + kk + lh) * 2));
#pragma unroll
            for (int nbp = 0; nbp < 8; nbp++) {
                uint32_t b[4];
                ldsm4t(b, stb + (uint32_t)(((kk + (q & 1) * 8 + r7) * EBP + dwp + (nbp * 2 + (q >> 1)) * 8) * 2));
                mma_bf16(acc[2 * nbp],     a, b);
                mma_bf16(acc[2 * nbp + 1], a, b + 2);
            }
        }
        if (c + 1 < NCk) {
            *(uint4*)&sA[nbuf][ar * AP + ac] = cvt8bf(av[0], av[1]);
#pragma unroll
            for (int p = 0; p < 4; p++) *(uint4*)&sB[nbuf][wk * EBP + wd + p * 8] = wr[p];
        }
        __syncthreads();
        buf = nbuf;
    }

    int gi = lane >> 2, gk = (lane & 3) * 2;
    int r0 = iwp + gi, r1 = r0 + 8;
    float s0 = 0.f, q0 = 0.f, s1 = 0.f, q1 = 0.f;
#pragma unroll
    for (int nb = 0; nb < 16; nb++) {
        int d = dwp + nb * 8 + gk;
        float2 b2 = *(const float2*)&b_out[d];
        float2 x0 = *(const float2*)&X[(size_t)(i0 + r0) * DD + d];
        float2 x1 = *(const float2*)&X[(size_t)(i0 + r1) * DD + d];
        acc[nb][0] += b2.x + x0.x; acc[nb][1] += b2.y + x0.y;
        acc[nb][2] += b2.x + x1.x; acc[nb][3] += b2.y + x1.y;
        s0 += acc[nb][0] + acc[nb][1]; q0 += acc[nb][0] * acc[nb][0] + acc[nb][1] * acc[nb][1];
        s1 += acc[nb][2] + acc[nb][3]; q1 += acc[nb][2] * acc[nb][2] + acc[nb][3] * acc[nb][3];
    }
#pragma unroll
    for (int o = 1; o <= 2; o <<= 1) {
        s0 += __shfl_xor_sync(0xFFFFFFFFu, s0, o);
        q0 += __shfl_xor_sync(0xFFFFFFFFu, q0, o);
        s1 += __shfl_xor_sync(0xFFFFFFFFu, s1, o);
        q1 += __shfl_xor_sync(0xFFFFFFFFu, q1, o);
    }
    int dwi = w >> 2;
    if (gk == 0) {
        red[r0][dwi] = make_float2(s0, q0);
        red[r1][dwi] = make_float2(s1, q1);
    }
    __syncthreads();
    float2 ra0 = red[r0][0], rb0 = red[r0][1];
    float2 ra1 = red[r1][0], rb1 = red[r1][1];
    float mu0 = (ra0.x + rb0.x) * (1.f / 256.f);
    float mu1 = (ra1.x + rb1.x) * (1.f / 256.f);
    float v0  = (ra0.y + rb0.y) * (1.f / 256.f) - mu0 * mu0;
    float v1  = (ra1.y + rb1.y) * (1.f / 256.f) - mu1 * mu1;
    float rs0 = rsqrtf(v0 + LN_EPS), rs1 = rsqrtf(v1 + LN_EPS);
#pragma unroll
    for (int nb = 0; nb < 16; nb++) {
        int d = dwp + nb * 8 + gk;
        float2 ls = *(const float2*)&ln_s[d];
        float2 lb = *(const float2*)&ln_b[d];
        *(float2*)&out[(size_t)(i0 + r0) * DD + d] =
            make_float2((acc[nb][0] - mu0) * rs0 * ls.x + lb.x,
                        (acc[nb][1] - mu0) * rs0 * ls.y + lb.y);
        *(float2*)&out[(size_t)(i0 + r1) * DD + d] =
            make_float2((acc[nb][2] - mu1) * rs1 * ls.x + lb.x,
                        (acc[nb][3] - mu1) * rs1 * ls.y + lb.y);
    }
}

// ================= launch =================
extern "C" void kernel_launch(void* const* d_in, const int* in_sizes, int n_in,
                              void* d_out, int out_size) {
    const float* X     = (const float*)d_in[0];
    const float* M     = (const float*)d_in[1];
    const float* W_in  = (const float*)d_in[2];
    const float* b_in  = (const float*)d_in[3];
    const float* W_out = (const float*)d_in[4];
    const float* b_out = (const float*)d_in[5];
    const float* ln_s  = (const float*)d_in[6];
    const float* ln_b  = (const float*)d_in[7];
    float* out = (float*)d_out;

    colsum_kernel<<<256, 256>>>(M);
    prep_kernel  <<<256, 256>>>(W_in, W_out);
    t_kernel     <<<128, 256>>>(X, b_in);
    mma_kernel   <<<296, 256>>>(M);
    epi_kernel   <<<128, 256>>>(X, b_out, ln_s, ln_b, out);
}